// round 8
// baseline (speedup 1.0000x reference)
#include <cuda_runtime.h>
#include <cuda_fp16.h>
#include <cstdint>
#include <cstddef>

// ---------------- problem dims ----------------
#define BATCH 2048
#define NDIM  4096      // output features (m,n,o)
#define KDIM  4096      // input features  (i,j,k)

#define W_SCALE 16384.0f
#define W_INV   (1.0f / 16384.0f)

// ---------------- device scratch (no allocations allowed) ----------------
__device__ __align__(16) float  g_FM[1 << 20];                   // 4 MB  FM[i,m,j,n,s]
__device__ __align__(16) __half g_WT[(size_t)NDIM * KDIM];       // 32 MB WT[row=mno][col=ijk]
__device__ __align__(16) __half g_X [(size_t)BATCH * KDIM];      // 16 MB x in fp16

// ---------------- helpers (sm_103-legal PTX only: cp.async, ldmatrix, mma.sync) ----
static __device__ __forceinline__ uint32_t smem_u32(const void* p) {
    uint32_t a;
    asm("{ .reg .u64 t; cvta.to.shared.u64 t, %1; cvt.u32.u64 %0, t; }" : "=r"(a) : "l"(p));
    return a;
}

static __device__ __forceinline__ void cp_async16(uint32_t s, const void* g) {
    asm volatile("cp.async.cg.shared.global [%0], [%1], 16;" :: "r"(s), "l"(g) : "memory");
}

static __device__ __forceinline__ void ldsm4(uint32_t r[4], uint32_t addr) {
    asm volatile("ldmatrix.sync.aligned.m8n8.x4.shared.b16 {%0,%1,%2,%3}, [%4];"
                 : "=r"(r[0]), "=r"(r[1]), "=r"(r[2]), "=r"(r[3]) : "r"(addr));
}

static __device__ __forceinline__ void mma16816(float c[4], const uint32_t a[4],
                                                const uint32_t b[2]) {
    asm volatile(
        "mma.sync.aligned.m16n8k16.row.col.f32.f16.f16.f32 "
        "{%0,%1,%2,%3}, {%4,%5,%6,%7}, {%8,%9}, {%0,%1,%2,%3};"
        : "+f"(c[0]), "+f"(c[1]), "+f"(c[2]), "+f"(c[3])
        : "r"(a[0]), "r"(a[1]), "r"(a[2]), "r"(a[3]), "r"(b[0]), "r"(b[1]));
}

// ======================================================================
// Kernel 1: FM[i,m,j,n,s] = sum_r F[i,r,m] * M[j,r,s,n]
// ======================================================================
__global__ void fm_kernel(const float* __restrict__ Fc, const float* __restrict__ Mc) {
    __shared__ float sF[4096];
    const int tid = threadIdx.x;
    #pragma unroll
    for (int i = tid; i < 4096; i += 256) sF[i] = Fc[i];
    __syncthreads();
    const unsigned t = blockIdx.x * 256u + tid;     // 16^5 threads total
    const int s = t & 15, n = (t >> 4) & 15, j = (t >> 8) & 15,
              m = (t >> 12) & 15, i = t >> 16;
    const float* fp = sF + i * 256 + m;             // F[i, r, m], stride 16 in r
    const float* mp = Mc + j * 4096 + s * 16 + n;   // M[j, r, s, n], stride 256 in r
    float acc = 0.f;
    #pragma unroll
    for (int r = 0; r < 16; ++r) acc = fmaf(fp[r * 16], mp[r * 256], acc);
    g_FM[t] = acc;
}

// ======================================================================
// Kernel 2: WT[row=(m,n,o)][col=(i,j,k)] = SCALE * sum_s FM[i,m,j,n,s] * L[k,s,o]
// ======================================================================
__global__ void w_kernel(const float* __restrict__ L) {
    __shared__ float sL[256];                        // L[k, s, o] for fixed o: [k*16+s]
    const unsigned t0 = blockIdx.x * 256u;
    const unsigned row = t0 >> 12;                   // constant within block
    const int o = row & 15;
    const int tid = threadIdx.x;
    sL[tid] = L[(tid >> 4) * 256 + (tid & 15) * 16 + o];   // tid = k*16 + s
    __syncthreads();
    const unsigned t = t0 + tid;
    const int col = t & 4095;
    const int k = col & 15, j = (col >> 4) & 15, i = col >> 8;
    const int n = (row >> 4) & 15, m = (row >> 8) & 15;
    const float* fm = g_FM + (((((i << 4) | m) << 4 | j) << 4 | n) << 4);
    float acc = 0.f;
    #pragma unroll
    for (int s = 0; s < 16; ++s) acc = fmaf(fm[s], sL[k * 16 + s], acc);
    g_WT[t] = __float2half_rn(acc * W_SCALE);
}

// ======================================================================
// Kernel 3: x fp32 -> fp16
// ======================================================================
__global__ void xcvt_kernel(const float* __restrict__ x) {
    const unsigned t = blockIdx.x * 256u + threadIdx.x;   // BATCH*KDIM/4 threads
    const float4 v = ((const float4*)x)[t];
    __half2 a = __floats2half2_rn(v.x, v.y);
    __half2 b = __floats2half2_rn(v.z, v.w);
    uint2 u;
    u.x = *(const uint32_t*)&a;
    u.y = *(const uint32_t*)&b;
    ((uint2*)g_X)[t] = u;
}

// ======================================================================
// Kernel 4: GEMM  out[b, mno] = (x_fp16 @ WT^T) * W_INV + bias
// mma.sync m16n8k16 (fallback HMMA), BM=128 BN=128 BK=64, 3-stage cp.async
// ======================================================================
#define BM 128
#define BN 128
#define BK 64
#define STAGES 3
#define KT (KDIM / BK)                    // 64
#define A_STAGE (BM * 128)                // 16 KB (128 rows x 128B)
#define B_STAGE (BN * 128)                // 16 KB
#define STAGE_BYTES (A_STAGE + B_STAGE)   // 32 KB
#define DYN_SMEM (STAGES * STAGE_BYTES)   // 96 KB

__global__ void __launch_bounds__(256, 2)
gemm_kernel(const float* __restrict__ bias, float* __restrict__ out) {
    extern __shared__ char dsm[];
    const uint32_t sbase = smem_u32(dsm);
    __shared__ float sbias[BN];

    const int tid = threadIdx.x;
    const int wid = tid >> 5;
    const int lid = tid & 31;
    const int warp_m = wid >> 2;              // 0..1 -> m offset *64
    const int warp_n = wid & 3;               // 0..3 -> n offset *32
    const int m_base = blockIdx.y * BM;
    const int n_base = blockIdx.x * BN;

    if (tid < BN) sbias[tid] = bias[n_base + tid];

    const __half* __restrict__ Xg = g_X;
    const __half* __restrict__ Wg = g_WT;

    auto load_stage = [&](int slot, int kt) {
        const uint32_t sb = sbase + slot * STAGE_BYTES;
        const int kcol = kt * BK;
        #pragma unroll
        for (int it = 0; it < 4; ++it) {          // A: 1024 x 16B chunks
            int c = tid + it * 256;
            int row = c >> 3, cu = c & 7;
            cp_async16(sb + row * 128 + ((cu ^ (row & 7)) << 4),
                       Xg + (size_t)(m_base + row) * KDIM + kcol + cu * 8);
        }
        #pragma unroll
        for (int it = 0; it < 4; ++it) {          // B: 1024 x 16B chunks
            int c = tid + it * 256;
            int row = c >> 3, cu = c & 7;
            cp_async16(sb + A_STAGE + row * 128 + ((cu ^ (row & 7)) << 4),
                       Wg + (size_t)(n_base + row) * KDIM + kcol + cu * 8);
        }
    };

    #pragma unroll
    for (int s = 0; s < STAGES - 1; ++s) {
        load_stage(s, s);
        asm volatile("cp.async.commit_group;" ::: "memory");
    }

    float acc[4][4][4];
    #pragma unroll
    for (int a = 0; a < 4; ++a)
        #pragma unroll
        for (int b = 0; b < 4; ++b)
            #pragma unroll
            for (int c = 0; c < 4; ++c) acc[a][b][c] = 0.f;

    const int quad = lid >> 3;     // which 8x8 matrix this lane addresses
    const int lrow = lid & 7;

    for (int kt = 0; kt < KT; ++kt) {
        asm volatile("cp.async.wait_group 1;" ::: "memory");
        __syncthreads();
        const uint32_t aBase = sbase + (kt % STAGES) * STAGE_BYTES;
        const uint32_t bBase = aBase + A_STAGE;

        #pragma unroll
        for (int ks = 0; ks < BK / 16; ++ks) {
            uint32_t afr[4][4], bfr[2][4];
            #pragma unroll
            for (int fm = 0; fm < 4; ++fm) {
                // x4: mat0 rows m..m+7 kLo, mat1 m+8..15 kLo, mat2 kHi, mat3 m+8 kHi
                int row = warp_m * 64 + fm * 16 + (quad & 1) * 8 + lrow;
                int cu  = ks * 2 + (quad >> 1);
                ldsm4(afr[fm], aBase + row * 128 + ((cu ^ (row & 7)) << 4));
            }
            #pragma unroll
            for (int g = 0; g < 2; ++g) {
                // x4: mat0 n..n+7 kLo, mat1 n..n+7 kHi, mat2 n+8 kLo, mat3 n+8 kHi
                int row = warp_n * 32 + g * 16 + (quad >> 1) * 8 + lrow;
                int cu  = ks * 2 + (quad & 1);
                ldsm4(bfr[g], bBase + row * 128 + ((cu ^ (row & 7)) << 4));
            }
            #pragma unroll
            for (int fm = 0; fm < 4; ++fm)
                #pragma unroll
                for (int fn = 0; fn < 4; ++fn)
                    mma16816(acc[fm][fn], afr[fm], &bfr[fn >> 1][(fn & 1) * 2]);
        }

        const int next = kt + STAGES - 1;
        if (next < KT) load_stage(next % STAGES, next);
        asm volatile("cp.async.commit_group;" ::: "memory");
    }

    // Epilogue: d frag layout: c0,c1 = row g, cols 2t,2t+1; c2,c3 = row g+8
    const int g = lid >> 2, t4 = lid & 3;
    #pragma unroll
    for (int fm = 0; fm < 4; ++fm) {
        const int row0 = m_base + warp_m * 64 + fm * 16 + g;
        #pragma unroll
        for (int fn = 0; fn < 4; ++fn) {
            const int cn = warp_n * 32 + fn * 8 + t4 * 2;
            float2 v0, v1;
            v0.x = acc[fm][fn][0] * W_INV + sbias[cn];
            v0.y = acc[fm][fn][1] * W_INV + sbias[cn + 1];
            v1.x = acc[fm][fn][2] * W_INV + sbias[cn];
            v1.y = acc[fm][fn][3] * W_INV + sbias[cn + 1];
            *(float2*)(out + (size_t)row0 * NDIM + n_base + cn) = v0;
            *(float2*)(out + (size_t)(row0 + 8) * NDIM + n_base + cn) = v1;
        }
    }
}

// ======================================================================
// launch
// ======================================================================
extern "C" void kernel_launch(void* const* d_in, const int* in_sizes, int n_in,
                              void* d_out, int out_size) {
    const float* x    = (const float*)d_in[0];
    const float* Fc   = (const float*)d_in[1];
    const float* Mc   = (const float*)d_in[2];
    const float* Lc   = (const float*)d_in[3];
    const float* bias = (const float*)d_in[4];
    float* out = (float*)d_out;

    cudaFuncSetAttribute(gemm_kernel, cudaFuncAttributeMaxDynamicSharedMemorySize, DYN_SMEM);

    fm_kernel<<<(1 << 20) / 256, 256>>>(Fc, Mc);
    w_kernel<<<(1 << 24) / 256, 256>>>(Lc);
    xcvt_kernel<<<(BATCH * KDIM / 4) / 256, 256>>>(x);

    dim3 grid(NDIM / BN, BATCH / BM);
    gemm_kernel<<<grid, 256, DYN_SMEM>>>(bias, out);
}

// round 13
// speedup vs baseline: 1.3852x; 1.3852x over previous
#include <cuda_runtime.h>
#include <cuda_fp16.h>
#include <cstdint>
#include <cstddef>

// ---------------- problem dims ----------------
#define BATCH 2048
#define NDIM  4096      // output features (m,n,o)
#define KDIM  4096      // input features  (i,j,k)

#define W_SCALE 16384.0f
#define W_INV   (1.0f / 16384.0f)

// ---------------- device scratch (no allocations allowed) ----------------
__device__ __align__(16) float  g_FM[1 << 20];                   // 4 MB  FM[i,m,j,n,s]
__device__ __align__(16) __half g_WT[(size_t)NDIM * KDIM];       // 32 MB WT[row=mno][col=ijk]
__device__ __align__(16) __half g_X [(size_t)BATCH * KDIM];      // 16 MB x in fp16

// ---------------- helpers (sm_103-legal PTX only: cp.async, ldmatrix, mma.sync) ----
static __device__ __forceinline__ uint32_t smem_u32(const void* p) {
    uint32_t a;
    asm("{ .reg .u64 t; cvta.to.shared.u64 t, %1; cvt.u32.u64 %0, t; }" : "=r"(a) : "l"(p));
    return a;
}

static __device__ __forceinline__ void cp_async16(uint32_t s, const void* g) {
    asm volatile("cp.async.cg.shared.global [%0], [%1], 16;" :: "r"(s), "l"(g) : "memory");
}

static __device__ __forceinline__ void ldsm4(uint32_t r[4], uint32_t addr) {
    asm volatile("ldmatrix.sync.aligned.m8n8.x4.shared.b16 {%0,%1,%2,%3}, [%4];"
                 : "=r"(r[0]), "=r"(r[1]), "=r"(r[2]), "=r"(r[3]) : "r"(addr));
}

static __device__ __forceinline__ void mma16816(float c[4], const uint32_t a[4],
                                                const uint32_t b[2]) {
    asm volatile(
        "mma.sync.aligned.m16n8k16.row.col.f32.f16.f16.f32 "
        "{%0,%1,%2,%3}, {%4,%5,%6,%7}, {%8,%9}, {%0,%1,%2,%3};"
        : "+f"(c[0]), "+f"(c[1]), "+f"(c[2]), "+f"(c[3])
        : "r"(a[0]), "r"(a[1]), "r"(a[2]), "r"(a[3]), "r"(b[0]), "r"(b[1]));
}

// ======================================================================
// Kernel 1: FM[i,m,j,n,s] = sum_r F[i,r,m] * M[j,r,s,n]
// ======================================================================
__global__ void fm_kernel(const float* __restrict__ Fc, const float* __restrict__ Mc) {
    __shared__ float sF[4096];
    const int tid = threadIdx.x;
    #pragma unroll
    for (int i = tid; i < 4096; i += 256) sF[i] = Fc[i];
    __syncthreads();
    const unsigned t = blockIdx.x * 256u + tid;     // 16^5 threads total
    const int s = t & 15, n = (t >> 4) & 15, j = (t >> 8) & 15,
              m = (t >> 12) & 15, i = t >> 16;
    const float* fp = sF + i * 256 + m;             // F[i, r, m], stride 16 in r
    const float* mp = Mc + j * 4096 + s * 16 + n;   // M[j, r, s, n], stride 256 in r
    float acc = 0.f;
    #pragma unroll
    for (int r = 0; r < 16; ++r) acc = fmaf(fp[r * 16], mp[r * 256], acc);
    g_FM[t] = acc;
}

// ======================================================================
// Kernel 2 (rewritten): WT[row=(m,n,o)][col=(i,j,k)]
//   = SCALE * sum_s FM[i,m,j,n,s] * L[k,s,o]
// One block per (m,n,i). L staged in smem (direct copy, conflict-free reads
// with lanes over o). FM slice (j,s) staged in smem, then registered.
// Each thread: fixed (j,o), computes 16 k outputs, writes 32B contiguous.
// ======================================================================
__global__ void w_kernel(const float* __restrict__ L) {
    __shared__ float sL[4096];      // sL[k*256 + s*16 + o] = L[k,s,o]
    __shared__ float sFM[256];      // sFM[j*16 + s] = FM[i,m,j,n,s]
    const int tid = threadIdx.x;
    const int bid = blockIdx.x;
    const int i = bid & 15, n = (bid >> 4) & 15, m = bid >> 8;

    #pragma unroll
    for (int idx = tid; idx < 4096; idx += 256) sL[idx] = L[idx];
    {
        const int jj = tid >> 4, ss = tid & 15;
        sFM[tid] = g_FM[i * 65536 + m * 4096 + jj * 256 + n * 16 + ss];
    }
    __syncthreads();

    const int j = tid >> 4, o = tid & 15;
    float fm[16];
    #pragma unroll
    for (int s = 0; s < 16; ++s) fm[s] = sFM[j * 16 + s];

    __half h[16];
    #pragma unroll
    for (int k = 0; k < 16; ++k) {
        float acc = 0.f;
        #pragma unroll
        for (int s = 0; s < 16; ++s)
            acc = fmaf(fm[s], sL[k * 256 + s * 16 + o], acc);
        h[k] = __float2half_rn(acc * W_SCALE);
    }

    const size_t row = (size_t)(m * 256 + n * 16 + o);
    uint4* dst = (uint4*)(g_WT + row * KDIM + i * 256 + j * 16);
    dst[0] = ((const uint4*)h)[0];
    dst[1] = ((const uint4*)h)[1];
}

// ======================================================================
// Kernel 3: x fp32 -> fp16
// ======================================================================
__global__ void xcvt_kernel(const float* __restrict__ x) {
    const unsigned t = blockIdx.x * 256u + threadIdx.x;   // BATCH*KDIM/4 threads
    const float4 v = ((const float4*)x)[t];
    __half2 a = __floats2half2_rn(v.x, v.y);
    __half2 b = __floats2half2_rn(v.z, v.w);
    uint2 u;
    u.x = *(const uint32_t*)&a;
    u.y = *(const uint32_t*)&b;
    ((uint2*)g_X)[t] = u;
}

// ======================================================================
// Kernel 4: GEMM  out[b, mno] = (x_fp16 @ WT^T) * W_INV + bias
// mma.sync m16n8k16 (fallback HMMA), BM=128 BN=128 BK=64, 3-stage cp.async
// ======================================================================
#define BM 128
#define BN 128
#define BK 64
#define STAGES 3
#define KT (KDIM / BK)                    // 64
#define A_STAGE (BM * 128)                // 16 KB (128 rows x 128B)
#define B_STAGE (BN * 128)                // 16 KB
#define STAGE_BYTES (A_STAGE + B_STAGE)   // 32 KB
#define DYN_SMEM (STAGES * STAGE_BYTES)   // 96 KB

__global__ void __launch_bounds__(256, 2)
gemm_kernel(const float* __restrict__ bias, float* __restrict__ out) {
    extern __shared__ char dsm[];
    const uint32_t sbase = smem_u32(dsm);
    __shared__ float sbias[BN];

    const int tid = threadIdx.x;
    const int wid = tid >> 5;
    const int lid = tid & 31;
    const int warp_m = wid >> 2;              // 0..1 -> m offset *64
    const int warp_n = wid & 3;               // 0..3 -> n offset *32
    const int m_base = blockIdx.y * BM;
    const int n_base = blockIdx.x * BN;

    if (tid < BN) sbias[tid] = bias[n_base + tid];

    const __half* __restrict__ Xg = g_X;
    const __half* __restrict__ Wg = g_WT;

    auto load_stage = [&](int slot, int kt) {
        const uint32_t sb = sbase + slot * STAGE_BYTES;
        const int kcol = kt * BK;
        #pragma unroll
        for (int it = 0; it < 4; ++it) {          // A: 1024 x 16B chunks
            int c = tid + it * 256;
            int row = c >> 3, cu = c & 7;
            cp_async16(sb + row * 128 + ((cu ^ (row & 7)) << 4),
                       Xg + (size_t)(m_base + row) * KDIM + kcol + cu * 8);
        }
        #pragma unroll
        for (int it = 0; it < 4; ++it) {          // B: 1024 x 16B chunks
            int c = tid + it * 256;
            int row = c >> 3, cu = c & 7;
            cp_async16(sb + A_STAGE + row * 128 + ((cu ^ (row & 7)) << 4),
                       Wg + (size_t)(n_base + row) * KDIM + kcol + cu * 8);
        }
    };

    #pragma unroll
    for (int s = 0; s < STAGES - 1; ++s) {
        load_stage(s, s);
        asm volatile("cp.async.commit_group;" ::: "memory");
    }

    float acc[4][4][4];
    #pragma unroll
    for (int a = 0; a < 4; ++a)
        #pragma unroll
        for (int b = 0; b < 4; ++b)
            #pragma unroll
            for (int c = 0; c < 4; ++c) acc[a][b][c] = 0.f;

    const int quad = lid >> 3;     // which 8x8 matrix this lane addresses
    const int lrow = lid & 7;

    for (int kt = 0; kt < KT; ++kt) {
        asm volatile("cp.async.wait_group 1;" ::: "memory");
        __syncthreads();

        // Issue next-stage loads FIRST so cp.async overlaps the MMA burst.
        // Safe: slot (kt+2)%3 == slot (kt-1)%3 was fully consumed before the
        // __syncthreads above.
        const int next = kt + STAGES - 1;
        if (next < KT) load_stage(next % STAGES, next);
        asm volatile("cp.async.commit_group;" ::: "memory");

        const uint32_t aBase = sbase + (kt % STAGES) * STAGE_BYTES;
        const uint32_t bBase = aBase + A_STAGE;

        #pragma unroll
        for (int ks = 0; ks < BK / 16; ++ks) {
            uint32_t afr[4][4], bfr[2][4];
            #pragma unroll
            for (int fm = 0; fm < 4; ++fm) {
                int row = warp_m * 64 + fm * 16 + (quad & 1) * 8 + lrow;
                int cu  = ks * 2 + (quad >> 1);
                ldsm4(afr[fm], aBase + row * 128 + ((cu ^ (row & 7)) << 4));
            }
            #pragma unroll
            for (int g = 0; g < 2; ++g) {
                int row = warp_n * 32 + g * 16 + (quad >> 1) * 8 + lrow;
                int cu  = ks * 2 + (quad & 1);
                ldsm4(bfr[g], bBase + row * 128 + ((cu ^ (row & 7)) << 4));
            }
            #pragma unroll
            for (int fm = 0; fm < 4; ++fm)
                #pragma unroll
                for (int fn = 0; fn < 4; ++fn)
                    mma16816(acc[fm][fn], afr[fm], &bfr[fn >> 1][(fn & 1) * 2]);
        }
    }

    // Epilogue: d frag layout: c0,c1 = row g, cols 2t,2t+1; c2,c3 = row g+8
    const int g = lid >> 2, t4 = lid & 3;
    #pragma unroll
    for (int fm = 0; fm < 4; ++fm) {
        const int row0 = m_base + warp_m * 64 + fm * 16 + g;
        #pragma unroll
        for (int fn = 0; fn < 4; ++fn) {
            const int cn = warp_n * 32 + fn * 8 + t4 * 2;
            float2 v0, v1;
            v0.x = acc[fm][fn][0] * W_INV + sbias[cn];
            v0.y = acc[fm][fn][1] * W_INV + sbias[cn + 1];
            v1.x = acc[fm][fn][2] * W_INV + sbias[cn];
            v1.y = acc[fm][fn][3] * W_INV + sbias[cn + 1];
            *(float2*)(out + (size_t)row0 * NDIM + n_base + cn) = v0;
            *(float2*)(out + (size_t)(row0 + 8) * NDIM + n_base + cn) = v1;
        }
    }
}

// ======================================================================
// launch
// ======================================================================
extern "C" void kernel_launch(void* const* d_in, const int* in_sizes, int n_in,
                              void* d_out, int out_size) {
    const float* x    = (const float*)d_in[0];
    const float* Fc   = (const float*)d_in[1];
    const float* Mc   = (const float*)d_in[2];
    const float* Lc   = (const float*)d_in[3];
    const float* bias = (const float*)d_in[4];
    float* out = (float*)d_out;

    cudaFuncSetAttribute(gemm_kernel, cudaFuncAttributeMaxDynamicSharedMemorySize, DYN_SMEM);

    fm_kernel<<<(1 << 20) / 256, 256>>>(Fc, Mc);
    w_kernel<<<4096, 256>>>(Lc);
    xcvt_kernel<<<(BATCH * KDIM / 4) / 256, 256>>>(x);

    dim3 grid(NDIM / BN, BATCH / BM);
    gemm_kernel<<<grid, 256, DYN_SMEM>>>(bias, out);
}

// round 15
// speedup vs baseline: 1.7065x; 1.2320x over previous
#include <cuda_runtime.h>
#include <cuda_fp16.h>
#include <cstdint>
#include <cstddef>

// ---------------- problem dims ----------------
#define BATCH 2048
#define NDIM  4096      // output features (m,n,o)
#define KDIM  4096      // input features  (i,j,k)

#define W_SCALE 16384.0f
#define W_INV   (1.0f / 16384.0f)

// ---------------- device scratch (no allocations allowed) ----------------
__device__ __align__(16) float  g_FM[1 << 20];                   // 4 MB  FM[i,m,j,n,s]
__device__ __align__(16) __half g_WT[(size_t)NDIM * KDIM];       // 32 MB WT[row=mno][col=ijk]
__device__ __align__(16) __half g_X [(size_t)BATCH * KDIM];      // 16 MB x in fp16

// ---------------- helpers (sm_103-legal PTX only: cp.async, ldmatrix, mma.sync) ----
static __device__ __forceinline__ uint32_t smem_u32(const void* p) {
    uint32_t a;
    asm("{ .reg .u64 t; cvta.to.shared.u64 t, %1; cvt.u32.u64 %0, t; }" : "=r"(a) : "l"(p));
    return a;
}

static __device__ __forceinline__ void cp_async16(uint32_t s, const void* g) {
    asm volatile("cp.async.cg.shared.global [%0], [%1], 16;" :: "r"(s), "l"(g) : "memory");
}

static __device__ __forceinline__ void ldsm4(uint32_t r[4], uint32_t addr) {
    asm volatile("ldmatrix.sync.aligned.m8n8.x4.shared.b16 {%0,%1,%2,%3}, [%4];"
                 : "=r"(r[0]), "=r"(r[1]), "=r"(r[2]), "=r"(r[3]) : "r"(addr));
}

static __device__ __forceinline__ void mma16816(float c[4], const uint32_t a[4],
                                                const uint32_t b[2]) {
    asm volatile(
        "mma.sync.aligned.m16n8k16.row.col.f32.f16.f16.f32 "
        "{%0,%1,%2,%3}, {%4,%5,%6,%7}, {%8,%9}, {%0,%1,%2,%3};"
        : "+f"(c[0]), "+f"(c[1]), "+f"(c[2]), "+f"(c[3])
        : "r"(a[0]), "r"(a[1]), "r"(a[2]), "r"(a[3]), "r"(b[0]), "r"(b[1]));
}

// ======================================================================
// Kernel 1: FM[i,m,j,n,s] = sum_r F[i,r,m] * M[j,r,s,n]
// One block per (i,j). M[j] staged in smem with padded layout (s*17+n) so
// compute reads (lanes vary s,n) are bank-conflict-free. Per thread (n,s):
// cache M[r] in 16 regs (reused across all 16 m), F reads are broadcasts.
// ======================================================================
__global__ void fm_kernel(const float* __restrict__ Fc, const float* __restrict__ Mc) {
    __shared__ float sF[256];          // F[i][r][m] -> sF[r*16+m]
    __shared__ float sM[16 * 272];     // M[j][r][s][n] -> sM[r*272 + s*17 + n]
    const int tid = threadIdx.x;
    const int bid = blockIdx.x;        // 256 blocks: i = bid>>4, j = bid&15
    const int i = bid >> 4, j = bid & 15;

    sF[tid] = Fc[i * 256 + tid];
    #pragma unroll
    for (int it = 0; it < 16; ++it) {
        int idx = tid + it * 256;                  // r*256 + s*16 + n
        int r = idx >> 8, s = (idx >> 4) & 15, nn = idx & 15;
        sM[r * 272 + s * 17 + nn] = Mc[j * 4096 + idx];
    }
    __syncthreads();

    const int n = tid >> 4, s = tid & 15;          // output addr low bits n*16+s = tid
    float mv[16];
    #pragma unroll
    for (int r = 0; r < 16; ++r) mv[r] = sM[r * 272 + s * 17 + n];

    float* dst = g_FM + i * 65536 + j * 256 + tid; // + m*4096 in loop
    #pragma unroll
    for (int m = 0; m < 16; ++m) {
        float acc = 0.f;
        #pragma unroll
        for (int r = 0; r < 16; ++r) acc = fmaf(sF[r * 16 + m], mv[r], acc);
        dst[m * 4096] = acc;
    }
}

// ======================================================================
// Kernel 2: WT[row=(m,n,o)][col=(i,j,k)] = SCALE * sum_s FM[i,m,j,n,s]*L[k,s,o]
// One block per (m,n), all 16 i per block, i chunked by 4 so each sL read
// feeds 4 FMAs. Thread = (j = tid&15, o = tid>>4).
// ======================================================================
__global__ void w_kernel(const float* __restrict__ L) {
    __shared__ float sL[4096];         // [k][s][o] natural layout
    __shared__ float sFM[16 * 272];    // [i][j*17 + s]
    const int tid = threadIdx.x;
    const int bid = blockIdx.x;        // 256 blocks: m = bid>>4, n = bid&15
    const int m = bid >> 4, n = bid & 15;

    #pragma unroll
    for (int it = 0; it < 16; ++it) sL[tid + it * 256] = L[tid + it * 256];
    #pragma unroll
    for (int it = 0; it < 16; ++it) {
        int idx = tid + it * 256;                  // i*256 + j*16 + s
        int i = idx >> 8, jj = (idx >> 4) & 15, ss = idx & 15;
        sFM[i * 272 + jj * 17 + ss] =
            g_FM[i * 65536 + m * 4096 + jj * 256 + n * 16 + ss];
    }
    __syncthreads();

    const int j = tid & 15, o = tid >> 4;
    const size_t row = (size_t)(m * 256 + n * 16 + o);
    __half* wrow = g_WT + row * KDIM + j * 16;

    #pragma unroll
    for (int i0 = 0; i0 < 16; i0 += 4) {
        float fm[4][16];
        #pragma unroll
        for (int ii = 0; ii < 4; ++ii)
            #pragma unroll
            for (int s = 0; s < 16; ++s)
                fm[ii][s] = sFM[(i0 + ii) * 272 + j * 17 + s];

        __half h[4][16];
        #pragma unroll
        for (int k = 0; k < 16; ++k) {
            float acc0 = 0.f, acc1 = 0.f, acc2 = 0.f, acc3 = 0.f;
            #pragma unroll
            for (int s = 0; s < 16; ++s) {
                const float lv = sL[k * 256 + s * 16 + o];
                acc0 = fmaf(fm[0][s], lv, acc0);
                acc1 = fmaf(fm[1][s], lv, acc1);
                acc2 = fmaf(fm[2][s], lv, acc2);
                acc3 = fmaf(fm[3][s], lv, acc3);
            }
            h[0][k] = __float2half_rn(acc0 * W_SCALE);
            h[1][k] = __float2half_rn(acc1 * W_SCALE);
            h[2][k] = __float2half_rn(acc2 * W_SCALE);
            h[3][k] = __float2half_rn(acc3 * W_SCALE);
        }
        #pragma unroll
        for (int ii = 0; ii < 4; ++ii) {
            uint4* dst = (uint4*)(wrow + (i0 + ii) * 256);
            dst[0] = ((const uint4*)h[ii])[0];
            dst[1] = ((const uint4*)h[ii])[1];
        }
    }
}

// ======================================================================
// Kernel 3: x fp32 -> fp16
// ======================================================================
__global__ void xcvt_kernel(const float* __restrict__ x) {
    const unsigned t = blockIdx.x * 256u + threadIdx.x;   // BATCH*KDIM/4 threads
    const float4 v = ((const float4*)x)[t];
    __half2 a = __floats2half2_rn(v.x, v.y);
    __half2 b = __floats2half2_rn(v.z, v.w);
    uint2 u;
    u.x = *(const uint32_t*)&a;
    u.y = *(const uint32_t*)&b;
    ((uint2*)g_X)[t] = u;
}

// ======================================================================
// Kernel 4: GEMM  out[b, mno] = (x_fp16 @ WT^T) * W_INV + bias
// mma.sync m16n8k16 (fallback HMMA), BM=128 BN=128 BK=64, 3-stage cp.async
// R8 loop ordering (MMA burst first, next-stage loads after).
// ======================================================================
#define BM 128
#define BN 128
#define BK 64
#define STAGES 3
#define KT (KDIM / BK)                    // 64
#define A_STAGE (BM * 128)                // 16 KB (128 rows x 128B)
#define B_STAGE (BN * 128)                // 16 KB
#define STAGE_BYTES (A_STAGE + B_STAGE)   // 32 KB
#define DYN_SMEM (STAGES * STAGE_BYTES)   // 96 KB

__global__ void __launch_bounds__(256, 2)
gemm_kernel(const float* __restrict__ bias, float* __restrict__ out) {
    extern __shared__ char dsm[];
    const uint32_t sbase = smem_u32(dsm);
    __shared__ float sbias[BN];

    const int tid = threadIdx.x;
    const int wid = tid >> 5;
    const int lid = tid & 31;
    const int warp_m = wid >> 2;              // 0..1 -> m offset *64
    const int warp_n = wid & 3;               // 0..3 -> n offset *32
    const int m_base = blockIdx.y * BM;
    const int n_base = blockIdx.x * BN;

    if (tid < BN) sbias[tid] = bias[n_base + tid];   // GUARD: BN=128 < blockDim

    const __half* __restrict__ Xg = g_X;
    const __half* __restrict__ Wg = g_WT;

    auto load_stage = [&](int slot, int kt) {
        const uint32_t sb = sbase + slot * STAGE_BYTES;
        const int kcol = kt * BK;
        #pragma unroll
        for (int it = 0; it < 4; ++it) {          // A: 1024 x 16B chunks
            int c = tid + it * 256;
            int row = c >> 3, cu = c & 7;
            cp_async16(sb + row * 128 + ((cu ^ (row & 7)) << 4),
                       Xg + (size_t)(m_base + row) * KDIM + kcol + cu * 8);
        }
        #pragma unroll
        for (int it = 0; it < 4; ++it) {          // B: 1024 x 16B chunks
            int c = tid + it * 256;
            int row = c >> 3, cu = c & 7;
            cp_async16(sb + A_STAGE + row * 128 + ((cu ^ (row & 7)) << 4),
                       Wg + (size_t)(n_base + row) * KDIM + kcol + cu * 8);
        }
    };

    #pragma unroll
    for (int s = 0; s < STAGES - 1; ++s) {
        load_stage(s, s);
        asm volatile("cp.async.commit_group;" ::: "memory");
    }

    float acc[4][4][4];
    #pragma unroll
    for (int a = 0; a < 4; ++a)
        #pragma unroll
        for (int b = 0; b < 4; ++b)
            #pragma unroll
            for (int c = 0; c < 4; ++c) acc[a][b][c] = 0.f;

    const int quad = lid >> 3;     // which 8x8 matrix this lane addresses
    const int lrow = lid & 7;

    for (int kt = 0; kt < KT; ++kt) {
        asm volatile("cp.async.wait_group 1;" ::: "memory");
        __syncthreads();
        const uint32_t aBase = sbase + (kt % STAGES) * STAGE_BYTES;
        const uint32_t bBase = aBase + A_STAGE;

        #pragma unroll
        for (int ks = 0; ks < BK / 16; ++ks) {
            uint32_t afr[4][4], bfr[2][4];
            #pragma unroll
            for (int fm = 0; fm < 4; ++fm) {
                int row = warp_m * 64 + fm * 16 + (quad & 1) * 8 + lrow;
                int cu  = ks * 2 + (quad >> 1);
                ldsm4(afr[fm], aBase + row * 128 + ((cu ^ (row & 7)) << 4));
            }
            #pragma unroll
            for (int g = 0; g < 2; ++g) {
                int row = warp_n * 32 + g * 16 + (quad >> 1) * 8 + lrow;
                int cu  = ks * 2 + (quad & 1);
                ldsm4(bfr[g], bBase + row * 128 + ((cu ^ (row & 7)) << 4));
            }
            #pragma unroll
            for (int fm = 0; fm < 4; ++fm)
                #pragma unroll
                for (int fn = 0; fn < 4; ++fn)
                    mma16816(acc[fm][fn], afr[fm], &bfr[fn >> 1][(fn & 1) * 2]);
        }

        const int next = kt + STAGES - 1;
        if (next < KT) load_stage(next % STAGES, next);
        asm volatile("cp.async.commit_group;" ::: "memory");
    }

    // Epilogue: d frag layout: c0,c1 = row g, cols 2t,2t+1; c2,c3 = row g+8
    const int g = lid >> 2, t4 = lid & 3;
    #pragma unroll
    for (int fm = 0; fm < 4; ++fm) {
        const int row0 = m_base + warp_m * 64 + fm * 16 + g;
        #pragma unroll
        for (int fn = 0; fn < 4; ++fn) {
            const int cn = warp_n * 32 + fn * 8 + t4 * 2;
            float2 v0, v1;
            v0.x = acc[fm][fn][0] * W_INV + sbias[cn];
            v0.y = acc[fm][fn][1] * W_INV + sbias[cn + 1];
            v1.x = acc[fm][fn][2] * W_INV + sbias[cn];
            v1.y = acc[fm][fn][3] * W_INV + sbias[cn + 1];
            *(float2*)(out + (size_t)row0 * NDIM + n_base + cn) = v0;
            *(float2*)(out + (size_t)(row0 + 8) * NDIM + n_base + cn) = v1;
        }
    }
}

// ======================================================================
// launch
// ======================================================================
extern "C" void kernel_launch(void* const* d_in, const int* in_sizes, int n_in,
                              void* d_out, int out_size) {
    const float* x    = (const float*)d_in[0];
    const float* Fc   = (const float*)d_in[1];
    const float* Mc   = (const float*)d_in[2];
    const float* Lc   = (const float*)d_in[3];
    const float* bias = (const float*)d_in[4];
    float* out = (float*)d_out;

    cudaFuncSetAttribute(gemm_kernel, cudaFuncAttributeMaxDynamicSharedMemorySize, DYN_SMEM);

    fm_kernel<<<256, 256>>>(Fc, Mc);
    w_kernel<<<256, 256>>>(Lc);
    xcvt_kernel<<<(BATCH * KDIM / 4) / 256, 256>>>(x);

    dim3 grid(NDIM / BN, BATCH / BM);
    gemm_kernel<<<grid, 256, DYN_SMEM>>>(bias, out);
}